// round 10
// baseline (speedup 1.0000x reference)
#include <cuda_runtime.h>
#include <cuda_bf16.h>
#include <math.h>
#include <stdint.h>

#define NN 50000
#define EE 800000
#define GG 512
#define LN_EPS 1e-5f
#define NEG_SLOPE 0.2f
#define NCHUNKS ((NN + 1023) / 1024)

// ---------------- device scratch ----------------
__device__ float g_xl[NN * 256];
__device__ float g_xr[NN * 256];
__device__ float g_h[NN * 256];
__device__ float g_acc[NN * 256];
__device__ int   g_rowptr[NN + 1];
__device__ int   g_cnt[NN];
__device__ int   g_eidx[EE];            // holds SRC node id per CSR slot
__device__ int   g_part[64];
__device__ float g_red[6];              // (sum, sumsq) per layer
__device__ float g_pool[GG * 64];
__device__ float g_pcnt[GG];

__device__ __forceinline__ float lrelu(float v) {
    return v > 0.f ? v : NEG_SLOPE * v;
}

__device__ __forceinline__ uint32_t smem_u32(const void* p) {
    uint32_t a;
    asm("{ .reg .u64 t; cvta.to.shared.u64 t, %1; cvt.u32.u64 %0, t; }" : "=r"(a) : "l"(p));
    return a;
}

__device__ __forceinline__ void cp16(uint32_t dst, const void* src, int srcsize) {
    asm volatile("cp.async.cg.shared.global [%0], [%1], 16, %2;"
                 :: "r"(dst), "l"(src), "r"(srcsize) : "memory");
}
#define CP_COMMIT() asm volatile("cp.async.commit_group;" ::: "memory")
#define CP_WAIT1()  asm volatile("cp.async.wait_group 1;" ::: "memory")
#define CP_WAIT0()  asm volatile("cp.async.wait_group 0;" ::: "memory")

// packed dual-fp32 FMA (Blackwell FFMA2). d = a*b + d, lanewise on 2x f32.
#define FMA_F32X2(d, a, b) \
    asm("fma.rn.f32x2 %0, %1, %2, %0;" : "+l"(d) : "l"(a), "l"(b))
#define BCAST_F32X2(d, s) \
    asm("mov.b64 %0, {%1, %1};" : "=l"(d) : "r"(__float_as_uint(s)))

// ---------------- init / CSR build ----------------
__global__ void k_zero_misc() {
    int i = blockIdx.x * blockDim.x + threadIdx.x;
    if (i < NN) g_cnt[i] = 0;
    if (i < GG * 64) g_pool[i] = 0.f;
    if (i < GG) g_pcnt[i] = 0.f;
    if (i < 6) g_red[i] = 0.f;
}

__global__ void k_hist_pcnt(const int* __restrict__ dst, const int* __restrict__ batch) {
    int e = blockIdx.x * blockDim.x + threadIdx.x;
    if (e < EE) atomicAdd(&g_cnt[dst[e]], 1);
    if (e < NN) atomicAdd(&g_pcnt[batch[e]], 1.f);
}

// 3-pass scan
__global__ __launch_bounds__(1024) void k_scan1() {
    __shared__ int sh[1024];
    int b = blockIdx.x;
    int tid = threadIdx.x;
    int i = b * 1024 + tid;
    int v = (i < NN) ? g_cnt[i] : 0;
    sh[tid] = v;
    __syncthreads();
    #pragma unroll
    for (int off = 1; off < 1024; off <<= 1) {
        int t = (tid >= off) ? sh[tid - off] : 0;
        __syncthreads();
        sh[tid] += t;
        __syncthreads();
    }
    if (i < NN) g_rowptr[i + 1] = sh[tid];
    if (tid == 1023) g_part[b] = sh[1023];
}

__global__ __launch_bounds__(64) void k_scan2() {
    __shared__ int sh[64];
    int tid = threadIdx.x;
    int v = (tid < NCHUNKS) ? g_part[tid] : 0;
    sh[tid] = v;
    __syncthreads();
    #pragma unroll
    for (int off = 1; off < 64; off <<= 1) {
        int t = (tid >= off) ? sh[tid - off] : 0;
        __syncthreads();
        sh[tid] += t;
        __syncthreads();
    }
    g_part[tid] = sh[tid] - v;
}

__global__ void k_scan3() {
    int i = blockIdx.x * blockDim.x + threadIdx.x;
    if (i == 0) g_rowptr[0] = 0;
    if (i < NN) {
        int incl = g_rowptr[i + 1] + g_part[i >> 10];
        g_rowptr[i + 1] = incl;
        g_cnt[i] = incl - g_cnt[i];   // scatter cursor (exclusive)
    }
}

// store SRC id directly (edge id never needed downstream)
__global__ void k_scatter(const int* __restrict__ src, const int* __restrict__ dst) {
    int e = blockIdx.x * blockDim.x + threadIdx.x;
    if (e < EE) {
        int pos = atomicAdd(&g_cnt[dst[e]], 1);
        g_eidx[pos] = src[e];
    }
}

// ---------------- fused dual GEMM: 3-stage cp.async + FFMA2 packed math ----
// Combined-width GEMM over [Wl | Wr] (2M cols). Block tile 128x128,
// 256 threads, 8x8 micro-tile (as 8x4 packed f32x2 pairs), BK=16,
// 3-stage cp.async ring, register fragment double-buffering.
template <int K, int M>
__global__ __launch_bounds__(256, 2) void k_gemm_dual(
    const float* __restrict__ X,
    const float* __restrict__ Wl, const float* __restrict__ bl,
    const float* __restrict__ Wr, const float* __restrict__ br,
    float* __restrict__ Yl, float* __restrict__ Yr, int rows)
{
    constexpr int NC = K / 16;
    __shared__ float As[3][128][20];    // row-major A chunk, 20-float pitch
    __shared__ float Bs[3][16][132];    // 132*4=528B row pitch (16B aligned)

    int block_row = blockIdx.y * 128;
    int block_col = blockIdx.x * 128;
    int t = threadIdx.x;
    int tx = t & 15;
    int ty = t >> 4;

    uint32_t sA = smem_u32(&As[0][0][0]);
    uint32_t sB = smem_u32(&Bs[0][0][0]);
    constexpr uint32_t A_BUF = 128 * 20 * 4;
    constexpr uint32_t B_BUF = 16 * 132 * 4;

    int a_r[2], a_q[2];
    #pragma unroll
    for (int it = 0; it < 2; it++) {
        int slot = t + it * 256;
        a_r[it] = slot >> 2;
        a_q[it] = slot & 3;
    }
    int b_k[2], b_n[2];
    const float* Wp[2];
    #pragma unroll
    for (int it = 0; it < 2; it++) {
        int slot = t + it * 256;
        b_k[it] = slot >> 5;
        b_n[it] = (slot & 31) * 4;
        int gc = block_col + b_n[it];
        Wp[it] = (gc < M) ? (Wl + gc) : (Wr + gc - M);
    }

    // packed accumulators: acc2[i][j] = (acc[i][2j], acc[i][2j+1])
    unsigned long long acc2[8][4];
    #pragma unroll
    for (int i = 0; i < 8; i++)
        #pragma unroll
        for (int j = 0; j < 4; j++) acc2[i][j] = 0ull;

    auto issue_copy = [&](int c, int buf) {
        int k0 = c * 16;
        #pragma unroll
        for (int it = 0; it < 2; it++) {
            int grow = block_row + a_r[it];
            uint32_t dst = sA + buf * A_BUF + (a_r[it] * 20 + a_q[it] * 4) * 4;
            cp16(dst, X + (size_t)grow * K + k0 + a_q[it] * 4, (grow < rows) ? 16 : 0);
        }
        #pragma unroll
        for (int it = 0; it < 2; it++) {
            uint32_t dst = sB + buf * B_BUF + (b_k[it] * 132 + b_n[it]) * 4;
            cp16(dst, Wp[it] + (size_t)(k0 + b_k[it]) * M, 16);
        }
        CP_COMMIT();
    };

    issue_copy(0, 0);
    if (NC > 1) issue_copy(1, 1);

    #pragma unroll 1
    for (int c = 0; c < NC; c++) {
        int cb = c % 3;
        if (c + 1 < NC) { CP_WAIT1(); } else { CP_WAIT0(); }
        __syncthreads();
        if (c + 2 < NC) issue_copy(c + 2, (c + 2) % 3);

        const float* pA = &As[cb][ty * 8][0];
        const float* pB = &Bs[cb][0][tx * 8];

        float fa[2][8];
        unsigned long long fb2[2][4];
        #pragma unroll
        for (int i = 0; i < 8; i++) fa[0][i] = pA[i * 20];
        {
            const ulonglong2* q = reinterpret_cast<const ulonglong2*>(pB);
            ulonglong2 v0 = q[0], v1 = q[1];
            fb2[0][0] = v0.x; fb2[0][1] = v0.y; fb2[0][2] = v1.x; fb2[0][3] = v1.y;
        }

        #pragma unroll
        for (int k = 0; k < 16; k++) {
            int cur = k & 1, nxt = (k + 1) & 1;
            if (k < 15) {
                #pragma unroll
                for (int i = 0; i < 8; i++) fa[nxt][i] = pA[i * 20 + k + 1];
                const ulonglong2* q = reinterpret_cast<const ulonglong2*>(pB + (k + 1) * 132);
                ulonglong2 v0 = q[0], v1 = q[1];
                fb2[nxt][0] = v0.x; fb2[nxt][1] = v0.y;
                fb2[nxt][2] = v1.x; fb2[nxt][3] = v1.y;
            }
            #pragma unroll
            for (int i = 0; i < 8; i++) {
                unsigned long long a2;
                BCAST_F32X2(a2, fa[cur][i]);
                #pragma unroll
                for (int j = 0; j < 4; j++)
                    FMA_F32X2(acc2[i][j], a2, fb2[cur][j]);
            }
        }
    }

    int gce = block_col + tx * 8;
    float* Y = (gce < M) ? Yl : Yr;
    const float* bb = (gce < M) ? bl : br;
    int col = (gce < M) ? gce : gce - M;
    float bv[8];
    #pragma unroll
    for (int j = 0; j < 8; j++) bv[j] = bb[col + j];

    #pragma unroll
    for (int i = 0; i < 8; i++) {
        int r = block_row + ty * 8 + i;
        if (r < rows) {
            float o[8];
            #pragma unroll
            for (int j = 0; j < 4; j++) {
                o[2 * j]     = __uint_as_float((unsigned)(acc2[i][j] & 0xffffffffull)) + bv[2 * j];
                o[2 * j + 1] = __uint_as_float((unsigned)(acc2[i][j] >> 32)) + bv[2 * j + 1];
            }
            *reinterpret_cast<float4*>(Y + (size_t)r * M + col) =
                make_float4(o[0], o[1], o[2], o[3]);
            *reinterpret_cast<float4*>(Y + (size_t)r * M + col + 4) =
                make_float4(o[4], o[5], o[6], o[7]);
        }
    }
}

// ---------------- edge attention + fused LN reduction ----------------
// One warp per destination node; online softmax; depth-1 gather pipeline.
template <int H>
__global__ __launch_bounds__(256) void k_edge_attn(
    const float* __restrict__ att,
    const float* __restrict__ bias,
    int layer)
{
    const int DM = H * 64;
    const unsigned FULL = 0xffffffffu;
    int warp = (blockIdx.x * blockDim.x + threadIdx.x) >> 5;
    int lane = threadIdx.x & 31;
    int wloc = threadIdx.x >> 5;
    int dn = warp;

    float sum = 0.f, sumsq = 0.f;

    if (dn < NN) {
        float xr0[H], xr1[H], at0[H], at1[H];
        #pragma unroll
        for (int h = 0; h < H; h++) {
            xr0[h] = g_xr[(size_t)dn * DM + h * 64 + lane];
            xr1[h] = g_xr[(size_t)dn * DM + h * 64 + lane + 32];
            at0[h] = att[h * 64 + lane];
            at1[h] = att[h * 64 + lane + 32];
        }

        int start = g_rowptr[dn];
        int end   = g_rowptr[dn + 1];

        float m[H], den[H], acc0[H], acc1[H];
        #pragma unroll
        for (int h = 0; h < H; h++) {
            m[h] = -INFINITY; den[h] = 0.f; acc0[h] = 0.f; acc1[h] = 0.f;
        }

        for (int base = start; base < end; base += 32) {
            int j = base + lane;
            int myS = (j < end) ? g_eidx[j] : 0;
            int cnt = min(32, end - base);

            float c0[H], c1[H];
            {
                int s0 = __shfl_sync(FULL, myS, 0);
                const float* row = &g_xl[(size_t)s0 * DM];
                #pragma unroll
                for (int h = 0; h < H; h++) {
                    c0[h] = row[h * 64 + lane];
                    c1[h] = row[h * 64 + lane + 32];
                }
            }

            for (int i = 0; i < cnt; i++) {
                float n0[H], n1[H];
                if (i + 1 < cnt) {
                    int sn = __shfl_sync(FULL, myS, i + 1);
                    const float* row = &g_xl[(size_t)sn * DM];
                    #pragma unroll
                    for (int h = 0; h < H; h++) {
                        n0[h] = row[h * 64 + lane];
                        n1[h] = row[h * 64 + lane + 32];
                    }
                }
                #pragma unroll
                for (int h = 0; h < H; h++) {
                    float p = lrelu(c0[h] + xr0[h]) * at0[h] + lrelu(c1[h] + xr1[h]) * at1[h];
                    #pragma unroll
                    for (int off = 16; off > 0; off >>= 1)
                        p += __shfl_xor_sync(FULL, p, off);
                    if (p > m[h]) {
                        float sc = __expf(m[h] - p);
                        den[h] *= sc; acc0[h] *= sc; acc1[h] *= sc;
                        m[h] = p;
                    }
                    float w = __expf(p - m[h]);
                    den[h] += w;
                    acc0[h] += w * c0[h];
                    acc1[h] += w * c1[h];
                }
                #pragma unroll
                for (int h = 0; h < H; h++) { c0[h] = n0[h]; c1[h] = n1[h]; }
            }
        }

        #pragma unroll
        for (int h = 0; h < H; h++) {
            float inv = (den[h] > 0.f) ? (1.f / den[h]) : 0.f;
            float o0 = acc0[h] * inv + bias[h * 64 + lane];
            float o1 = acc1[h] * inv + bias[h * 64 + lane + 32];
            g_acc[(size_t)dn * DM + h * 64 + lane]      = o0;
            g_acc[(size_t)dn * DM + h * 64 + lane + 32] = o1;
            sum   += o0 + o1;
            sumsq += o0 * o0 + o1 * o1;
        }
    }

    #pragma unroll
    for (int off = 16; off > 0; off >>= 1) {
        sum   += __shfl_xor_sync(FULL, sum,   off);
        sumsq += __shfl_xor_sync(FULL, sumsq, off);
    }
    __shared__ float sr[8], sr2[8];
    if (lane == 0) { sr[wloc] = sum; sr2[wloc] = sumsq; }
    __syncthreads();
    if (threadIdx.x == 0) {
        float a = 0.f, b = 0.f;
        #pragma unroll
        for (int i = 0; i < 8; i++) { a += sr[i]; b += sr2[i]; }
        atomicAdd(&g_red[2 * layer],     a);
        atomicAdd(&g_red[2 * layer + 1], b);
    }
}

// ---------------- LN apply (+relu, +residual, +optional pool) --------------
__global__ __launch_bounds__(256) void k_ln_apply(
    const float* __restrict__ gamma, const float* __restrict__ beta,
    const int* __restrict__ batch,
    int count, int DM, float invCount, int residual, int layer, int do_pool)
{
    int i = blockIdx.x * blockDim.x + threadIdx.x;
    if (i >= count) return;
    int c = i % DM;
    float mu  = g_red[2 * layer] * invCount;
    float var = g_red[2 * layer + 1] * invCount - mu * mu;
    float rs  = rsqrtf(var + LN_EPS);
    float v = (g_acc[i] - mu) * rs * gamma[c] + beta[c];
    v = fmaxf(v, 0.f);
    if (residual) v += g_h[i];
    g_h[i] = v;
    if (do_pool) {
        int node = i >> 6;
        atomicAdd(&g_pool[batch[node] * 64 + c], v);
    }
}

// ---------------- MLP head ----------------
__global__ __launch_bounds__(64) void k_mlp(
    const float* __restrict__ Wh1, const float* __restrict__ bh1,
    const float* __restrict__ Wh2, const float* __restrict__ bh2,
    float* __restrict__ out)
{
    int g = blockIdx.x;
    int j = threadIdx.x;
    __shared__ float z[64];
    __shared__ float red[64];
    float cnt = fmaxf(g_pcnt[g], 1.f);
    z[j] = g_pool[g * 64 + j] / cnt;
    __syncthreads();
    float hv = bh1[j];
    #pragma unroll 8
    for (int k = 0; k < 64; k++) hv += z[k] * Wh1[k * 64 + j];
    hv = fmaxf(hv, 0.f);
    red[j] = hv * Wh2[j];
    __syncthreads();
    for (int off = 32; off > 0; off >>= 1) {
        if (j < off) red[j] += red[j + off];
        __syncthreads();
    }
    if (j == 0) out[g] = red[0] + bh2[0];
}

// ---------------- host orchestration ----------------
extern "C" void kernel_launch(void* const* d_in, const int* in_sizes, int n_in,
                              void* d_out, int out_size)
{
    const float* x     = (const float*)d_in[0];
    const int*   ei    = (const int*)d_in[1];
    const int*   srcA  = ei;
    const int*   dstA  = ei + EE;
    const int*   batch = (const int*)d_in[2];

    const float* Wl[3];  const float* bl[3];
    const float* Wr[3];  const float* br[3];
    const float* att[3]; const float* bias[3];
    const float* lng[3]; const float* lnb[3];
    for (int l = 0; l < 3; l++) {
        int base = 3 + 8 * l;
        Wl[l]   = (const float*)d_in[base + 0];
        bl[l]   = (const float*)d_in[base + 1];
        Wr[l]   = (const float*)d_in[base + 2];
        br[l]   = (const float*)d_in[base + 3];
        att[l]  = (const float*)d_in[base + 4];
        bias[l] = (const float*)d_in[base + 5];
        lng[l]  = (const float*)d_in[base + 6];
        lnb[l]  = (const float*)d_in[base + 7];
    }
    const float* Wh1 = (const float*)d_in[27];
    const float* bh1 = (const float*)d_in[28];
    const float* Wh2 = (const float*)d_in[29];
    const float* bh2 = (const float*)d_in[30];
    float* out = (float*)d_out;

    float *p_xl, *p_xr, *p_h;
    cudaGetSymbolAddress((void**)&p_xl, g_xl);
    cudaGetSymbolAddress((void**)&p_xr, g_xr);
    cudaGetSymbolAddress((void**)&p_h,  g_h);

    const int dm_[3]  = {256, 64, 64};
    const int res_[3] = {0, 0, 1};
    const int RT = (NN + 127) / 128;
    const int edge_blocks = (NN * 32 + 255) / 256;

    k_zero_misc<<<(NN + 255) / 256, 256>>>();
    k_hist_pcnt<<<(EE + 255) / 256, 256>>>(dstA, batch);
    k_scan1<<<NCHUNKS, 1024>>>();
    k_gemm_dual<128, 256><<<dim3(4, RT), 256>>>(x, Wl[0], bl[0], Wr[0], br[0], p_xl, p_xr, NN);
    k_scan2<<<1, 64>>>();
    k_scan3<<<(NN + 255) / 256, 256>>>();
    k_scatter<<<(EE + 255) / 256, 256>>>(srcA, dstA);

    for (int l = 0; l < 3; l++) {
        if (l == 1)
            k_gemm_dual<256, 64><<<dim3(1, RT), 256>>>(p_h, Wl[1], bl[1], Wr[1], br[1], p_xl, p_xr, NN);
        else if (l == 2)
            k_gemm_dual<64, 64><<<dim3(1, RT), 256>>>(p_h, Wl[2], bl[2], Wr[2], br[2], p_xl, p_xr, NN);

        if (l == 0) k_edge_attn<4><<<edge_blocks, 256>>>(att[l], bias[l], l);
        else        k_edge_attn<1><<<edge_blocks, 256>>>(att[l], bias[l], l);

        int count = NN * dm_[l];
        k_ln_apply<<<(count + 255) / 256, 256>>>(lng[l], lnb[l], batch, count, dm_[l],
                                                 1.f / (float)count, res_[l], l, l == 2);
    }

    k_mlp<<<GG, 64>>>(Wh1, bh1, Wh2, bh2, out);

    (void)in_sizes; (void)n_in; (void)out_size;
}

// round 11
// speedup vs baseline: 1.1481x; 1.1481x over previous
#include <cuda_runtime.h>
#include <cuda_bf16.h>
#include <math.h>
#include <stdint.h>

#define NN 50000
#define EE 800000
#define GG 512
#define LN_EPS 1e-5f
#define NEG_SLOPE 0.2f
#define NCHUNKS ((NN + 1023) / 1024)

// ---------------- device scratch ----------------
__device__ float g_xl[NN * 256];
__device__ float g_xr[NN * 256];
__device__ float g_h[NN * 256];
__device__ float g_acc[NN * 256];
__device__ int   g_rowptr[NN + 1];
__device__ int   g_cnt[NN];
__device__ int   g_eidx[EE];            // holds SRC node id per CSR slot
__device__ int   g_part[64];
__device__ float g_red[6];              // (sum, sumsq) per layer
__device__ float g_pool[GG * 64];
__device__ float g_pcnt[GG];

__device__ __forceinline__ float lrelu(float v) {
    return v > 0.f ? v : NEG_SLOPE * v;
}

__device__ __forceinline__ uint32_t smem_u32(const void* p) {
    uint32_t a;
    asm("{ .reg .u64 t; cvta.to.shared.u64 t, %1; cvt.u32.u64 %0, t; }" : "=r"(a) : "l"(p));
    return a;
}

__device__ __forceinline__ void cp16(uint32_t dst, const void* src, int srcsize) {
    asm volatile("cp.async.cg.shared.global [%0], [%1], 16, %2;"
                 :: "r"(dst), "l"(src), "r"(srcsize) : "memory");
}
#define CP_COMMIT() asm volatile("cp.async.commit_group;" ::: "memory")
#define CP_WAIT1()  asm volatile("cp.async.wait_group 1;" ::: "memory")
#define CP_WAIT0()  asm volatile("cp.async.wait_group 0;" ::: "memory")

// ---------------- init / CSR build ----------------
__global__ void k_zero_misc() {
    int i = blockIdx.x * blockDim.x + threadIdx.x;
    if (i < NN) g_cnt[i] = 0;
    if (i < GG * 64) g_pool[i] = 0.f;
    if (i < GG) g_pcnt[i] = 0.f;
    if (i < 6) g_red[i] = 0.f;
}

__global__ void k_hist_pcnt(const int* __restrict__ dst, const int* __restrict__ batch) {
    int e = blockIdx.x * blockDim.x + threadIdx.x;
    if (e < EE) atomicAdd(&g_cnt[dst[e]], 1);
    if (e < NN) atomicAdd(&g_pcnt[batch[e]], 1.f);
}

// 3-pass scan
__global__ __launch_bounds__(1024) void k_scan1() {
    __shared__ int sh[1024];
    int b = blockIdx.x;
    int tid = threadIdx.x;
    int i = b * 1024 + tid;
    int v = (i < NN) ? g_cnt[i] : 0;
    sh[tid] = v;
    __syncthreads();
    #pragma unroll
    for (int off = 1; off < 1024; off <<= 1) {
        int t = (tid >= off) ? sh[tid - off] : 0;
        __syncthreads();
        sh[tid] += t;
        __syncthreads();
    }
    if (i < NN) g_rowptr[i + 1] = sh[tid];
    if (tid == 1023) g_part[b] = sh[1023];
}

__global__ __launch_bounds__(64) void k_scan2() {
    __shared__ int sh[64];
    int tid = threadIdx.x;
    int v = (tid < NCHUNKS) ? g_part[tid] : 0;
    sh[tid] = v;
    __syncthreads();
    #pragma unroll
    for (int off = 1; off < 64; off <<= 1) {
        int t = (tid >= off) ? sh[tid - off] : 0;
        __syncthreads();
        sh[tid] += t;
        __syncthreads();
    }
    g_part[tid] = sh[tid] - v;
}

__global__ void k_scan3() {
    int i = blockIdx.x * blockDim.x + threadIdx.x;
    if (i == 0) g_rowptr[0] = 0;
    if (i < NN) {
        int incl = g_rowptr[i + 1] + g_part[i >> 10];
        g_rowptr[i + 1] = incl;
        g_cnt[i] = incl - g_cnt[i];   // scatter cursor (exclusive)
    }
}

// store SRC id directly (edge id never needed downstream)
__global__ void k_scatter(const int* __restrict__ src, const int* __restrict__ dst) {
    int e = blockIdx.x * blockDim.x + threadIdx.x;
    if (e < EE) {
        int pos = atomicAdd(&g_cnt[dst[e]], 1);
        g_eidx[pos] = src[e];
    }
}

// ---------------- fused dual GEMM: 3-stage cp.async + fragment pipelining --
// (R9 configuration — measured at the FFMA roof; do not touch.)
template <int K, int M>
__global__ __launch_bounds__(256, 2) void k_gemm_dual(
    const float* __restrict__ X,
    const float* __restrict__ Wl, const float* __restrict__ bl,
    const float* __restrict__ Wr, const float* __restrict__ br,
    float* __restrict__ Yl, float* __restrict__ Yr, int rows)
{
    constexpr int NC = K / 16;
    __shared__ float As[3][128][20];
    __shared__ float Bs[3][16][132];

    int block_row = blockIdx.y * 128;
    int block_col = blockIdx.x * 128;
    int t = threadIdx.x;
    int tx = t & 15;
    int ty = t >> 4;

    uint32_t sA = smem_u32(&As[0][0][0]);
    uint32_t sB = smem_u32(&Bs[0][0][0]);
    constexpr uint32_t A_BUF = 128 * 20 * 4;
    constexpr uint32_t B_BUF = 16 * 132 * 4;

    int a_r[2], a_q[2];
    #pragma unroll
    for (int it = 0; it < 2; it++) {
        int slot = t + it * 256;
        a_r[it] = slot >> 2;
        a_q[it] = slot & 3;
    }
    int b_k[2], b_n[2];
    const float* Wp[2];
    #pragma unroll
    for (int it = 0; it < 2; it++) {
        int slot = t + it * 256;
        b_k[it] = slot >> 5;
        b_n[it] = (slot & 31) * 4;
        int gc = block_col + b_n[it];
        Wp[it] = (gc < M) ? (Wl + gc) : (Wr + gc - M);
    }

    float acc[8][8];
    #pragma unroll
    for (int i = 0; i < 8; i++)
        #pragma unroll
        for (int j = 0; j < 8; j++) acc[i][j] = 0.f;

    auto issue_copy = [&](int c, int buf) {
        int k0 = c * 16;
        #pragma unroll
        for (int it = 0; it < 2; it++) {
            int grow = block_row + a_r[it];
            uint32_t dst = sA + buf * A_BUF + (a_r[it] * 20 + a_q[it] * 4) * 4;
            cp16(dst, X + (size_t)grow * K + k0 + a_q[it] * 4, (grow < rows) ? 16 : 0);
        }
        #pragma unroll
        for (int it = 0; it < 2; it++) {
            uint32_t dst = sB + buf * B_BUF + (b_k[it] * 132 + b_n[it]) * 4;
            cp16(dst, Wp[it] + (size_t)(k0 + b_k[it]) * M, 16);
        }
        CP_COMMIT();
    };

    issue_copy(0, 0);
    if (NC > 1) issue_copy(1, 1);

    #pragma unroll 1
    for (int c = 0; c < NC; c++) {
        int cb = c % 3;
        if (c + 1 < NC) { CP_WAIT1(); } else { CP_WAIT0(); }
        __syncthreads();
        if (c + 2 < NC) issue_copy(c + 2, (c + 2) % 3);

        const float* pA = &As[cb][ty * 8][0];
        const float* pB = &Bs[cb][0][tx * 8];

        float fa[2][8], fb[2][8];
        #pragma unroll
        for (int i = 0; i < 8; i++) fa[0][i] = pA[i * 20];
        *reinterpret_cast<float4*>(&fb[0][0]) = *reinterpret_cast<const float4*>(pB);
        *reinterpret_cast<float4*>(&fb[0][4]) = *reinterpret_cast<const float4*>(pB + 4);

        #pragma unroll
        for (int k = 0; k < 16; k++) {
            int cur = k & 1, nxt = (k + 1) & 1;
            if (k < 15) {
                #pragma unroll
                for (int i = 0; i < 8; i++) fa[nxt][i] = pA[i * 20 + k + 1];
                const float* pBn = pB + (k + 1) * 132;
                *reinterpret_cast<float4*>(&fb[nxt][0]) = *reinterpret_cast<const float4*>(pBn);
                *reinterpret_cast<float4*>(&fb[nxt][4]) = *reinterpret_cast<const float4*>(pBn + 4);
            }
            #pragma unroll
            for (int i = 0; i < 8; i++)
                #pragma unroll
                for (int j = 0; j < 8; j++)
                    acc[i][j] += fa[cur][i] * fb[cur][j];
        }
    }

    int gce = block_col + tx * 8;
    float* Y = (gce < M) ? Yl : Yr;
    const float* bb = (gce < M) ? bl : br;
    int col = (gce < M) ? gce : gce - M;
    float bv[8];
    #pragma unroll
    for (int j = 0; j < 8; j++) bv[j] = bb[col + j];

    #pragma unroll
    for (int i = 0; i < 8; i++) {
        int r = block_row + ty * 8 + i;
        if (r < rows) {
            float4 o0, o1;
            o0.x = acc[i][0] + bv[0]; o0.y = acc[i][1] + bv[1];
            o0.z = acc[i][2] + bv[2]; o0.w = acc[i][3] + bv[3];
            o1.x = acc[i][4] + bv[4]; o1.y = acc[i][5] + bv[5];
            o1.z = acc[i][6] + bv[6]; o1.w = acc[i][7] + bv[7];
            *reinterpret_cast<float4*>(Y + (size_t)r * M + col)     = o0;
            *reinterpret_cast<float4*>(Y + (size_t)r * M + col + 4) = o1;
        }
    }
}

// ---------------- edge attention H=4, vectorized ----------------
// One warp per dst node. Lane owns floats [4l,4l+4) and [128+4l,128+4l+4)
// of the 256-float row: each 4-float chunk lies in a single head
// (chunk a -> head l>>4, chunk b -> head 2+(l>>4)). Logit reduce =
// 4-step butterfly within 16-lane groups; softmax state is group-local.
__global__ __launch_bounds__(256) void k_edge_attn4(
    const float* __restrict__ att,
    const float* __restrict__ bias,
    int layer)
{
    const unsigned FULL = 0xffffffffu;
    int warp = (blockIdx.x * blockDim.x + threadIdx.x) >> 5;
    int lane = threadIdx.x & 31;
    int wloc = threadIdx.x >> 5;
    int dn = warp;

    float sum = 0.f, sumsq = 0.f;

    if (dn < NN) {
        const float4* xr4 = reinterpret_cast<const float4*>(&g_xr[(size_t)dn * 256]);
        float4 xra = xr4[lane], xrb = xr4[lane + 32];
        const float4* at4 = reinterpret_cast<const float4*>(att);
        float4 ata = at4[lane], atb = at4[lane + 32];

        int start = g_rowptr[dn];
        int end   = g_rowptr[dn + 1];

        float m_a = -INFINITY, m_b = -INFINITY, den_a = 0.f, den_b = 0.f;
        float4 acca = make_float4(0.f, 0.f, 0.f, 0.f);
        float4 accb = make_float4(0.f, 0.f, 0.f, 0.f);

        for (int base = start; base < end; base += 32) {
            int j = base + lane;
            int myS = (j < end) ? g_eidx[j] : 0;
            int cnt = min(32, end - base);

            float4 va, vb;
            {
                int s0 = __shfl_sync(FULL, myS, 0);
                const float4* row = reinterpret_cast<const float4*>(&g_xl[(size_t)s0 * 256]);
                va = row[lane]; vb = row[lane + 32];
            }

            for (int i = 0; i < cnt; i++) {
                float4 na, nb;
                if (i + 1 < cnt) {
                    int sn = __shfl_sync(FULL, myS, i + 1);
                    const float4* row = reinterpret_cast<const float4*>(&g_xl[(size_t)sn * 256]);
                    na = row[lane]; nb = row[lane + 32];
                }
                float pa = lrelu(va.x + xra.x) * ata.x + lrelu(va.y + xra.y) * ata.y
                         + lrelu(va.z + xra.z) * ata.z + lrelu(va.w + xra.w) * ata.w;
                float pb = lrelu(vb.x + xrb.x) * atb.x + lrelu(vb.y + xrb.y) * atb.y
                         + lrelu(vb.z + xrb.z) * atb.z + lrelu(vb.w + xrb.w) * atb.w;
                #pragma unroll
                for (int off = 1; off < 16; off <<= 1) {
                    pa += __shfl_xor_sync(FULL, pa, off);
                    pb += __shfl_xor_sync(FULL, pb, off);
                }
                if (pa > m_a) {
                    float sc = __expf(m_a - pa);
                    den_a *= sc;
                    acca.x *= sc; acca.y *= sc; acca.z *= sc; acca.w *= sc;
                    m_a = pa;
                }
                float wa = __expf(pa - m_a);
                den_a += wa;
                acca.x += wa * va.x; acca.y += wa * va.y;
                acca.z += wa * va.z; acca.w += wa * va.w;

                if (pb > m_b) {
                    float sc = __expf(m_b - pb);
                    den_b *= sc;
                    accb.x *= sc; accb.y *= sc; accb.z *= sc; accb.w *= sc;
                    m_b = pb;
                }
                float wb = __expf(pb - m_b);
                den_b += wb;
                accb.x += wb * vb.x; accb.y += wb * vb.y;
                accb.z += wb * vb.z; accb.w += wb * vb.w;

                va = na; vb = nb;
            }
        }

        float inva = (den_a > 0.f) ? (1.f / den_a) : 0.f;
        float invb = (den_b > 0.f) ? (1.f / den_b) : 0.f;
        const float4* bi4 = reinterpret_cast<const float4*>(bias);
        float4 ba = bi4[lane], bbv = bi4[lane + 32];
        float4 oa, ob;
        oa.x = acca.x * inva + ba.x;  oa.y = acca.y * inva + ba.y;
        oa.z = acca.z * inva + ba.z;  oa.w = acca.w * inva + ba.w;
        ob.x = accb.x * invb + bbv.x; ob.y = accb.y * invb + bbv.y;
        ob.z = accb.z * invb + bbv.z; ob.w = accb.w * invb + bbv.w;
        float4* out4 = reinterpret_cast<float4*>(&g_acc[(size_t)dn * 256]);
        out4[lane] = oa;
        out4[lane + 32] = ob;
        sum   += oa.x + oa.y + oa.z + oa.w + ob.x + ob.y + ob.z + ob.w;
        sumsq += oa.x * oa.x + oa.y * oa.y + oa.z * oa.z + oa.w * oa.w
               + ob.x * ob.x + ob.y * ob.y + ob.z * ob.z + ob.w * ob.w;
    }

    #pragma unroll
    for (int off = 16; off > 0; off >>= 1) {
        sum   += __shfl_xor_sync(FULL, sum,   off);
        sumsq += __shfl_xor_sync(FULL, sumsq, off);
    }
    __shared__ float sr[8], sr2[8];
    if (lane == 0) { sr[wloc] = sum; sr2[wloc] = sumsq; }
    __syncthreads();
    if (threadIdx.x == 0) {
        float a = 0.f, b = 0.f;
        #pragma unroll
        for (int i = 0; i < 8; i++) { a += sr[i]; b += sr2[i]; }
        atomicAdd(&g_red[2 * layer],     a);
        atomicAdd(&g_red[2 * layer + 1], b);
    }
}

// ---------------- edge attention H=1, vectorized (float2/lane) -------------
__global__ __launch_bounds__(256) void k_edge_attn1(
    const float* __restrict__ att,
    const float* __restrict__ bias,
    int layer)
{
    const unsigned FULL = 0xffffffffu;
    int warp = (blockIdx.x * blockDim.x + threadIdx.x) >> 5;
    int lane = threadIdx.x & 31;
    int wloc = threadIdx.x >> 5;
    int dn = warp;

    float sum = 0.f, sumsq = 0.f;

    if (dn < NN) {
        float2 xr2 = reinterpret_cast<const float2*>(&g_xr[(size_t)dn * 64])[lane];
        float2 at2 = reinterpret_cast<const float2*>(att)[lane];

        int start = g_rowptr[dn];
        int end   = g_rowptr[dn + 1];

        float m = -INFINITY, den = 0.f;
        float2 acc = make_float2(0.f, 0.f);

        for (int base = start; base < end; base += 32) {
            int j = base + lane;
            int myS = (j < end) ? g_eidx[j] : 0;
            int cnt = min(32, end - base);

            float2 v;
            {
                int s0 = __shfl_sync(FULL, myS, 0);
                v = reinterpret_cast<const float2*>(&g_xl[(size_t)s0 * 64])[lane];
            }

            for (int i = 0; i < cnt; i++) {
                float2 nv;
                if (i + 1 < cnt) {
                    int sn = __shfl_sync(FULL, myS, i + 1);
                    nv = reinterpret_cast<const float2*>(&g_xl[(size_t)sn * 64])[lane];
                }
                float p = lrelu(v.x + xr2.x) * at2.x + lrelu(v.y + xr2.y) * at2.y;
                #pragma unroll
                for (int off = 1; off < 32; off <<= 1)
                    p += __shfl_xor_sync(FULL, p, off);
                if (p > m) {
                    float sc = __expf(m - p);
                    den *= sc; acc.x *= sc; acc.y *= sc;
                    m = p;
                }
                float w = __expf(p - m);
                den += w;
                acc.x += w * v.x;
                acc.y += w * v.y;
                v = nv;
            }
        }

        float inv = (den > 0.f) ? (1.f / den) : 0.f;
        float2 bi = reinterpret_cast<const float2*>(bias)[lane];
        float2 o;
        o.x = acc.x * inv + bi.x;
        o.y = acc.y * inv + bi.y;
        reinterpret_cast<float2*>(&g_acc[(size_t)dn * 64])[lane] = o;
        sum   += o.x + o.y;
        sumsq += o.x * o.x + o.y * o.y;
    }

    #pragma unroll
    for (int off = 16; off > 0; off >>= 1) {
        sum   += __shfl_xor_sync(FULL, sum,   off);
        sumsq += __shfl_xor_sync(FULL, sumsq, off);
    }
    __shared__ float sr[8], sr2[8];
    if (lane == 0) { sr[wloc] = sum; sr2[wloc] = sumsq; }
    __syncthreads();
    if (threadIdx.x == 0) {
        float a = 0.f, b = 0.f;
        #pragma unroll
        for (int i = 0; i < 8; i++) { a += sr[i]; b += sr2[i]; }
        atomicAdd(&g_red[2 * layer],     a);
        atomicAdd(&g_red[2 * layer + 1], b);
    }
}

// ---------------- LN apply (+relu, +residual, +optional pool) --------------
__global__ __launch_bounds__(256) void k_ln_apply(
    const float* __restrict__ gamma, const float* __restrict__ beta,
    const int* __restrict__ batch,
    int count, int DM, float invCount, int residual, int layer, int do_pool)
{
    int i = blockIdx.x * blockDim.x + threadIdx.x;
    if (i >= count) return;
    int c = i % DM;
    float mu  = g_red[2 * layer] * invCount;
    float var = g_red[2 * layer + 1] * invCount - mu * mu;
    float rs  = rsqrtf(var + LN_EPS);
    float v = (g_acc[i] - mu) * rs * gamma[c] + beta[c];
    v = fmaxf(v, 0.f);
    if (residual) v += g_h[i];
    g_h[i] = v;
    if (do_pool) {
        int node = i >> 6;
        atomicAdd(&g_pool[batch[node] * 64 + c], v);
    }
}

// ---------------- MLP head ----------------
__global__ __launch_bounds__(64) void k_mlp(
    const float* __restrict__ Wh1, const float* __restrict__ bh1,
    const float* __restrict__ Wh2, const float* __restrict__ bh2,
    float* __restrict__ out)
{
    int g = blockIdx.x;
    int j = threadIdx.x;
    __shared__ float z[64];
    __shared__ float red[64];
    float cnt = fmaxf(g_pcnt[g], 1.f);
    z[j] = g_pool[g * 64 + j] / cnt;
    __syncthreads();
    float hv = bh1[j];
    #pragma unroll 8
    for (int k = 0; k < 64; k++) hv += z[k] * Wh1[k * 64 + j];
    hv = fmaxf(hv, 0.f);
    red[j] = hv * Wh2[j];
    __syncthreads();
    for (int off = 32; off > 0; off >>= 1) {
        if (j < off) red[j] += red[j + off];
        __syncthreads();
    }
    if (j == 0) out[g] = red[0] + bh2[0];
}

// ---------------- host orchestration ----------------
extern "C" void kernel_launch(void* const* d_in, const int* in_sizes, int n_in,
                              void* d_out, int out_size)
{
    const float* x     = (const float*)d_in[0];
    const int*   ei    = (const int*)d_in[1];
    const int*   srcA  = ei;
    const int*   dstA  = ei + EE;
    const int*   batch = (const int*)d_in[2];

    const float* Wl[3];  const float* bl[3];
    const float* Wr[3];  const float* br[3];
    const float* att[3]; const float* bias[3];
    const float* lng[3]; const float* lnb[3];
    for (int l = 0; l < 3; l++) {
        int base = 3 + 8 * l;
        Wl[l]   = (const float*)d_in[base + 0];
        bl[l]   = (const float*)d_in[base + 1];
        Wr[l]   = (const float*)d_in[base + 2];
        br[l]   = (const float*)d_in[base + 3];
        att[l]  = (const float*)d_in[base + 4];
        bias[l] = (const float*)d_in[base + 5];
        lng[l]  = (const float*)d_in[base + 6];
        lnb[l]  = (const float*)d_in[base + 7];
    }
    const float* Wh1 = (const float*)d_in[27];
    const float* bh1 = (const float*)d_in[28];
    const float* Wh2 = (const float*)d_in[29];
    const float* bh2 = (const float*)d_in[30];
    float* out = (float*)d_out;

    float *p_xl, *p_xr, *p_h;
    cudaGetSymbolAddress((void**)&p_xl, g_xl);
    cudaGetSymbolAddress((void**)&p_xr, g_xr);
    cudaGetSymbolAddress((void**)&p_h,  g_h);

    const int dm_[3]  = {256, 64, 64};
    const int res_[3] = {0, 0, 1};
    const int RT = (NN + 127) / 128;
    const int edge_blocks = (NN * 32 + 255) / 256;

    k_zero_misc<<<(NN + 255) / 256, 256>>>();
    k_hist_pcnt<<<(EE + 255) / 256, 256>>>(dstA, batch);
    k_scan1<<<NCHUNKS, 1024>>>();
    k_gemm_dual<128, 256><<<dim3(4, RT), 256>>>(x, Wl[0], bl[0], Wr[0], br[0], p_xl, p_xr, NN);
    k_scan2<<<1, 64>>>();
    k_scan3<<<(NN + 255) / 256, 256>>>();
    k_scatter<<<(EE + 255) / 256, 256>>>(srcA, dstA);

    for (int l = 0; l < 3; l++) {
        if (l == 1)
            k_gemm_dual<256, 64><<<dim3(1, RT), 256>>>(p_h, Wl[1], bl[1], Wr[1], br[1], p_xl, p_xr, NN);
        else if (l == 2)
            k_gemm_dual<64, 64><<<dim3(1, RT), 256>>>(p_h, Wl[2], bl[2], Wr[2], br[2], p_xl, p_xr, NN);

        if (l == 0) k_edge_attn4<<<edge_blocks, 256>>>(att[l], bias[l], l);
        else        k_edge_attn1<<<edge_blocks, 256>>>(att[l], bias[l], l);

        int count = NN * dm_[l];
        k_ln_apply<<<(count + 255) / 256, 256>>>(lng[l], lnb[l], batch, count, dm_[l],
                                                 1.f / (float)count, res_[l], l, l == 2);
    }

    k_mlp<<<GG, 64>>>(Wh1, bh1, Wh2, bh2, out);

    (void)in_sizes; (void)n_in; (void)out_size;
}